// round 15
// baseline (speedup 1.0000x reference)
#include <cuda_runtime.h>
#include <cstdint>

#define NB 32
#define ND 256
#define NT 2048
#define NL 8
#define NK 1024
#define NVEC (NB*NT)
#define NOUT (NB*ND*NT)
#define NIDX (NB*NL*NT)

#define TM 128                       // rows per CTA
#define NTHREADS 512
#define TILEN 128                    // codes per wpack tile
#define NSTG 64                      // wpack stages (tile x dchunk)
#define NST2 32                      // mainloop super-stages (2 tiles wide)
#define CAP 32

// SMEM layout (bytes), single 512-thread CTA
#define ATF_OFF  0                   // A bf16 fragments: 4096 uint4 = 65536
#define RING_OFF 65536               // 16 warps x 3 stages x 2048B = 98304
#define NS_OFF   163840              // 1024 f32
#define AN_OFF   167936              // 128 f32
#define RM_OFF   168448              // 128 u32
#define CNT_OFF  168960              // 128 i32
#define RI_OFF   169472              // 128 i32
#define CD_OFF   169984              // 128*CAP u32 = 16384
#define PBV_OFF  186368              // 128*4 f32
#define PBI_OFF  188416              // 128*4 i32
#define SMEM_BYTES 190464            // < 227KB, 1 CTA/SM

// Scratch (static device allocations are the sanctioned workaround)
__device__ float    g_res[(size_t)NVEC * ND];
__device__ float    g_norms[NL * NK];
__device__ unsigned g_nsmax[NL];
__device__ uint4    g_wpack[NL * NSTG * 512];   // fragment-major bf16 codebook (4MB)

typedef unsigned long long ull;

// ---------------------------------------------------------------- helpers
__device__ __forceinline__ uint32_t bf2(float lo, float hi) {
    uint32_t r; asm("cvt.rn.bf16x2.f32 %0, %1, %2;" : "=r"(r) : "f"(hi), "f"(lo));
    return r;
}
__device__ __forceinline__ void mma_bf16(float* c, const uint32_t* a,
                                         uint32_t b0, uint32_t b1) {
    asm volatile(
        "mma.sync.aligned.m16n8k16.row.col.f32.bf16.bf16.f32 "
        "{%0,%1,%2,%3}, {%4,%5,%6,%7}, {%8,%9}, {%0,%1,%2,%3};"
        : "+f"(c[0]), "+f"(c[1]), "+f"(c[2]), "+f"(c[3])
        : "r"(a[0]), "r"(a[1]), "r"(a[2]), "r"(a[3]), "r"(b0), "r"(b1));
}
__device__ __forceinline__ ull pack2(float a, float b) {
    ull r; asm("mov.b64 %0, {%1, %2};" : "=l"(r) : "f"(a), "f"(b)); return r;
}
__device__ __forceinline__ float2 unpack2(ull v) {
    float2 r; asm("mov.b64 {%0, %1}, %2;" : "=f"(r.x), "=f"(r.y) : "l"(v)); return r;
}
__device__ __forceinline__ ull ffma2(ull a, ull b, ull c) {
    ull d; asm("fma.rn.f32x2 %0, %1, %2, %3;" : "=l"(d) : "l"(a), "l"(b), "l"(c));
    return d;
}
__device__ __forceinline__ ull fadd2(ull a, ull b) {
    ull d; asm("add.rn.f32x2 %0, %1, %2;" : "=l"(d) : "l"(a), "l"(b));
    return d;
}
__device__ __forceinline__ void cpasync16(uint32_t dst, const void* src) {
    asm volatile("cp.async.cg.shared.global [%0], [%1], 16;"
                 :: "r"(dst), "l"(src) : "memory");
}
#define CP_COMMIT() asm volatile("cp.async.commit_group;" ::: "memory")
#define CP_WAIT2()  asm volatile("cp.async.wait_group 2;" ::: "memory")
#define CP_WAIT0()  asm volatile("cp.async.wait_group 0;" ::: "memory")

// XLA-style warp row-reduce (mul then add, NO fma), xor-butterfly tree.
__device__ __forceinline__ float warp_sumsq_x32(const float* __restrict__ p, int lane) {
    float s = 0.f;
    #pragma unroll
    for (int i = 0; i < ND / 32; i++) {
        float v = p[lane + 32 * i];
        s = __fadd_rn(s, __fmul_rn(v, v));
    }
    #pragma unroll
    for (int o = 16; o; o >>= 1)
        s = __fadd_rn(s, __shfl_xor_sync(0xffffffffu, s, o));
    return s;
}

// exact dot chain (ascending d, fmaf) — validated rounding sequence.
__device__ __forceinline__ float dot_exact(const float4* __restrict__ a4,
                                           const float4* __restrict__ w4) {
    float acc = 0.f;
    #pragma unroll 8
    for (int q = 0; q < ND / 4; q++) {
        float4 av = a4[q], wv = w4[q];
        acc = __fmaf_rn(av.x, wv.x, acc);
        acc = __fmaf_rn(av.y, wv.y, acc);
        acc = __fmaf_rn(av.z, wv.z, acc);
        acc = __fmaf_rn(av.w, wv.w, acc);
    }
    return acc;
}

// ---------------------------------------------------------------- codebook norms
__global__ void norms_kernel(const float* __restrict__ cb) {
    int w    = (blockIdx.x * blockDim.x + threadIdx.x) >> 5;
    int lane = threadIdx.x & 31;
    if (w >= NL * NK) return;
    float s = warp_sumsq_x32(cb + (size_t)w * ND, lane);
    if (lane == 0) {
        g_norms[w] = s;
        atomicMax(&g_nsmax[w >> 10], __float_as_uint(s));
    }
}

// ---------------------------------------------------------------- pack codebook -> bf16 fragments
// slot within stage = ((kg*2+ng)*4+pp)*32 + lane; stage = ntile*8+dchunk
__global__ void pack_kernel(const float* __restrict__ cb) {
    int gid  = blockIdx.x * blockDim.x + threadIdx.x;   // 0 .. NL*64*512-1
    int lane = gid & 31;
    int s16  = (gid >> 5) & 15;
    int pp   = s16 & 3, ng = (s16 >> 2) & 1, kg = s16 >> 3;
    int st   = (gid >> 9) & 63;
    int l    = gid >> 15;
    int code = (st >> 3) * TILEN + ng * 64 + pp * 16 + (lane >> 2);
    int d    = (st & 7) * 32 + kg * 16 + (lane & 3) * 2;
    const float* w = cb + ((size_t)l * NK + code) * ND + d;
    uint4 v;
    v.x = bf2(w[0], w[1]);
    v.y = bf2(w[8], w[9]);
    v.z = bf2(w[8 * ND], w[8 * ND + 1]);
    v.w = bf2(w[8 * ND + 8], w[8 * ND + 9]);
    g_wpack[gid] = v;
}

// ---------------------------------------------------------------- x (B,D,T) -> res (N,D)
__global__ void tin_kernel(const float* __restrict__ x) {
    __shared__ float tile[32][33];
    int b  = blockIdx.z;
    int d0 = blockIdx.y * 32, t0 = blockIdx.x * 32;
    int tx = threadIdx.x, ty = threadIdx.y;
    #pragma unroll
    for (int i = 0; i < 32; i += 8)
        tile[ty + i][tx] = x[((size_t)b * ND + d0 + ty + i) * NT + t0 + tx];
    __syncthreads();
    #pragma unroll
    for (int i = 0; i < 32; i += 8)
        g_res[((size_t)(b * NT + t0 + ty + i)) * ND + d0 + tx] = tile[tx][ty + i];
}

// ---------------------------------------------------------------- out = x - res
__global__ void tout_kernel(const float* __restrict__ x, float* __restrict__ out) {
    __shared__ float tile[32][33];
    int b  = blockIdx.z;
    int d0 = blockIdx.y * 32, t0 = blockIdx.x * 32;
    int tx = threadIdx.x, ty = threadIdx.y;
    #pragma unroll
    for (int i = 0; i < 32; i += 8)
        tile[ty + i][tx] = g_res[((size_t)(b * NT + t0 + ty + i)) * ND + d0 + tx];
    __syncthreads();
    size_t base = (size_t)b * ND * NT;
    #pragma unroll
    for (int i = 0; i < 32; i += 8) {
        size_t o = base + (size_t)(d0 + ty + i) * NT + t0 + tx;
        out[o] = __fsub_rn(x[o], tile[tx][ty + i]);
    }
}

// ---------------------------------------------------------------- one RVQ layer
__global__ void __launch_bounds__(NTHREADS, 1) vq_layer_kernel(
    const float* __restrict__ codebooks,
    float* __restrict__ idx_out,
    int l, int write_idx)
{
    extern __shared__ char smem[];
    uint4*    Atf4   = (uint4*)(smem + ATF_OFF);
    float*    Ns     = (float*)(smem + NS_OFF);
    float*    An     = (float*)(smem + AN_OFF);
    uint32_t* runmin = (uint32_t*)(smem + RM_OFF);
    int*      cnt    = (int*)(smem + CNT_OFF);
    int*      RowIdx = (int*)(smem + RI_OFF);
    uint32_t* cand   = (uint32_t*)(smem + CD_OFF);
    float*    pbv    = (float*)(smem + PBV_OFF);
    int*      pbi    = (int*)(smem + PBI_OFF);

    uint32_t sbase;
    asm("{ .reg .u64 t; cvta.to.shared.u64 t, %1; cvt.u32.u64 %0, t; }"
        : "=r"(sbase) : "l"(smem));

    const float* W  = codebooks + (size_t)l * NK * ND;
    const int row0  = blockIdx.x * TM;
    const float* gA = g_res + (size_t)row0 * ND;
    const int tid   = threadIdx.x;
    const int lane  = tid & 31;
    const int warp  = tid >> 5;        // 0..15
    const int mg    = warp & 1;        // M-group (64 rows)
    const int ng    = warp >> 1;       // 0..7: super-tile N-group (256 codes)
    const int th    = ng >> 2;         // which 128-code wpack tile within pair
    const int ngi   = ng & 3;          // N-group within that tile (0..3)
    const int lr    = lane >> 2, lc = lane & 3;
    const float nsM = __uint_as_float(g_nsmax[l]);

    for (int i = tid; i < NK; i += NTHREADS) Ns[i] = g_norms[l * NK + i];
    if (tid < TM) { cnt[tid] = 0; runmin[tid] = 0x7F7FFFFFu; }

    // ---- |r|^2 per row, XLA reduce order ----
    #pragma unroll
    for (int rr = 0; rr < TM / 16; rr++) {
        int r = rr * 16 + warp;
        float s = warp_sumsq_x32(&gA[(size_t)r * ND], lane);
        if (lane == 0) An[r] = s;
    }

    // ---- pack A as bf16 m16n8k16 fragments (once per layer) ----
    #pragma unroll
    for (int i = 0; i < 4096 / NTHREADS; i++) {
        int s   = tid + i * NTHREADS;
        int lb  = s & 31, kq = (s >> 5) & 15, mt = (s >> 9) & 1, mgi = s >> 10;
        int r   = mgi * 32 + mt * 16 + (lb >> 2);
        int k0  = kq * 16 + (lb & 3) * 2;
        float2 x0 = *(const float2*)(gA + (size_t)r * ND + k0);
        float2 x1 = *(const float2*)(gA + (size_t)(r + 8) * ND + k0);
        float2 x2 = *(const float2*)(gA + (size_t)r * ND + k0 + 8);
        float2 x3 = *(const float2*)(gA + (size_t)(r + 8) * ND + k0 + 8);
        Atf4[s] = make_uint4(bf2(x0.x, x0.y), bf2(x1.x, x1.y),
                             bf2(x2.x, x2.y), bf2(x3.x, x3.y));
    }
    __syncthreads();     // A buffer ready; NO barriers in mainloop after this

    // ---- per-warp B fragment slot addresses in g_wpack (within-tile, uses ngi) ----
    const uint4* wp = (const uint4*)g_wpack + (size_t)l * NSTG * 512;
    const int ngh = ngi >> 1, ngl = ngi & 1;
    int sb[4];
    #pragma unroll
    for (int kg = 0; kg < 2; kg++)
        #pragma unroll
        for (int p = 0; p < 2; p++)
            sb[kg * 2 + p] = ((kg * 2 + ngh) * 4 + ngl * 2 + p) * 32 + lane;

    // wpack stage index for super-stage t: ((t>>3)*2 + th)*8 + (t&7)
    #define WSIDX(t) ((((t) >> 3) * 2 + th) * 8 + ((t) & 7))

    // per-warp private depth-3 cp.async ring: 3 x 2048B per warp
    const uint32_t ringAddr = sbase + RING_OFF + warp * (3 * 2048);
    const uint4*   ringRd   = (const uint4*)(smem + RING_OFF + warp * (3 * 2048));

    // prologue: super-stages 0 and 1 in flight
    #pragma unroll
    for (int s = 0; s < 2; s++) {
        #pragma unroll
        for (int q = 0; q < 4; q++)
            cpasync16(ringAddr + s * 2048 + q * 512 + lane * 16,
                      wp + (size_t)WSIDX(s) * 512 + sb[q]);
        CP_COMMIT();
    }

    const ull NEG2 = pack2(-2.f, -2.f);
    float accf[4][4][4];

    for (int t = 0; t < NST2; t++) {
        if ((t & 7) == 0) {
            #pragma unroll
            for (int a = 0; a < 4; a++)
                #pragma unroll
                for (int b = 0; b < 4; b++)
                    #pragma unroll
                    for (int c = 0; c < 4; c++) accf[a][b][c] = 0.f;
        }
        // prefetch super-stage t+2 (clamped; lands in consumed slot)
        {
            int pf = (t + 2 < NST2) ? t + 2 : NST2 - 1;
            int rs = (t + 2) % 3;
            #pragma unroll
            for (int q = 0; q < 4; q++)
                cpasync16(ringAddr + rs * 2048 + q * 512 + lane * 16,
                          wp + (size_t)WSIDX(pf) * 512 + sb[q]);
            CP_COMMIT();
        }
        CP_WAIT2();                       // stage t's group complete

        const uint4* bs = ringRd + (t % 3) * 128;   // 128 uint4 per stage slot
        #pragma unroll
        for (int kg = 0; kg < 2; kg++) {
            const int kq = (t & 7) * 2 + kg;
            uint4 B0 = bs[(kg * 2 + 0) * 32 + lane];
            uint4 B1 = bs[(kg * 2 + 1) * 32 + lane];
            uint4 Af[4];
            #pragma unroll
            for (int mt = 0; mt < 4; mt++)
                Af[mt] = Atf4[((mg * 4 + mt) * 16 + kq) * 32 + lane];
            #pragma unroll
            for (int mt = 0; mt < 4; mt++) {
                uint32_t a[4] = {Af[mt].x, Af[mt].y, Af[mt].z, Af[mt].w};
                mma_bf16(accf[mt][0], a, B0.x, B0.y);
                mma_bf16(accf[mt][1], a, B0.z, B0.w);
                mma_bf16(accf[mt][2], a, B1.x, B1.y);
                mma_bf16(accf[mt][3], a, B1.z, B1.w);
            }
        }

        // ---- per-tile epilogue (packed f32x2, single pass) ----
        if ((t & 7) == 7) {
            const int ntile = (t >> 3) * 2 + th;
            ull Ns2[4];
            #pragma unroll
            for (int ns = 0; ns < 4; ns++)
                Ns2[ns] = *(const ull*)&Ns[ntile * TILEN + ngi * 32 + (ns >> 1) * 16
                                           + (ns & 1) * 8 + 2 * lc];
            #pragma unroll
            for (int mt = 0; mt < 4; mt++) {
                #pragma unroll
                for (int h = 0; h < 2; h++) {
                    int row = mg * 64 + mt * 16 + lr + 8 * h;
                    float A  = An[row];
                    float ee = 0.0159f * sqrtf(A * nsM) + 0.25f;
                    ull  A2  = pack2(A, A);
                    float dl[8]; float m = 3.4e38f;
                    #pragma unroll
                    for (int ns = 0; ns < 4; ns++) {
                        // dv = rn(rn(A - 2*acc) + Ns): fma(-2,acc,A) exact-equal
                        // to sub(A, mul(2,acc)) since 2*acc is exact.
                        ull acc2 = pack2(accf[mt][ns][2 * h], accf[mt][ns][2 * h + 1]);
                        float2 e = unpack2(fadd2(ffma2(acc2, NEG2, A2), Ns2[ns]));
                        dl[2 * ns] = e.x; dl[2 * ns + 1] = e.y;
                        m = fminf(m, fminf(e.x, e.y));
                    }
                    float m2 = fminf(m, __shfl_xor_sync(0xffffffffu, m, 1));
                    m2 = fminf(m2, __shfl_xor_sync(0xffffffffu, m2, 2));
                    float rm  = __uint_as_float(runmin[row]);    // racy = conservative
                    float thr = fminf(m2, rm) + ee;
                    #pragma unroll
                    for (int e8 = 0; e8 < 8; e8++) {
                        if (dl[e8] <= thr) {
                            int col = ntile * TILEN + ngi * 32 + ((e8 >> 2) & 1) * 16
                                    + ((e8 >> 1) & 1) * 8 + 2 * lc + (e8 & 1);
                            int slot = atomicAdd(&cnt[row], 1);
                            if (slot < CAP)
                                cand[row * CAP + slot] =
                                    (__float_as_uint(fmaxf(dl[e8], 0.f)) & 0xFFFFFC00u)
                                    | (uint32_t)col;
                        }
                    }
                    if (lc == 0)
                        atomicMin(runmin + row, __float_as_uint(fmaxf(m2, 0.f)));
                }
            }
        }
    }
    CP_WAIT0();
    __syncthreads();

    // ---- exact rescore: 4-way per row, float4 + ILP-2 pairs (bit-identical) ----
    {
        int row = tid & (TM - 1), sl = tid >> 7;   // sl in 0..3
        float A = An[row];
        float thrF = __uint_as_float(runmin[row]) + (0.0159f * sqrtf(A * nsM) + 0.25f);
        int n = cnt[row];
        float bv = 3.4e38f; int bi = 1 << 30;
        const float4* a4 = (const float4*)(gA + (size_t)row * ND);
        if (n <= CAP) {
            int mycols[CAP / 4 + 1]; int mc = 0;
            for (int s = sl; s < n; s += 4) {
                uint32_t u = cand[row * CAP + s];
                if (__uint_as_float(u & 0xFFFFFC00u) > thrF) continue;
                mycols[mc++] = (int)(u & 1023u);
            }
            int i = 0;
            for (; i + 1 < mc; i += 2) {
                int c0 = mycols[i], c1 = mycols[i + 1];
                const float4* w0 = (const float4*)(W + (size_t)c0 * ND);
                const float4* w1 = (const float4*)(W + (size_t)c1 * ND);
                float acc0 = 0.f, acc1 = 0.f;
                #pragma unroll 8
                for (int q = 0; q < ND / 4; q++) {
                    float4 av = a4[q], v0 = w0[q], v1 = w1[q];
                    acc0 = __fmaf_rn(av.x, v0.x, acc0);
                    acc1 = __fmaf_rn(av.x, v1.x, acc1);
                    acc0 = __fmaf_rn(av.y, v0.y, acc0);
                    acc1 = __fmaf_rn(av.y, v1.y, acc1);
                    acc0 = __fmaf_rn(av.z, v0.z, acc0);
                    acc1 = __fmaf_rn(av.z, v1.z, acc1);
                    acc0 = __fmaf_rn(av.w, v0.w, acc0);
                    acc1 = __fmaf_rn(av.w, v1.w, acc1);
                }
                float d0 = __fadd_rn(__fsub_rn(A, __fmul_rn(2.f, acc0)), Ns[c0]);
                float d1 = __fadd_rn(__fsub_rn(A, __fmul_rn(2.f, acc1)), Ns[c1]);
                if (d0 < bv || (d0 == bv && c0 < bi)) { bv = d0; bi = c0; }
                if (d1 < bv || (d1 == bv && c1 < bi)) { bv = d1; bi = c1; }
            }
            if (i < mc) {
                int c0 = mycols[i];
                float acc = dot_exact(a4, (const float4*)(W + (size_t)c0 * ND));
                float de = __fadd_rn(__fsub_rn(A, __fmul_rn(2.f, acc)), Ns[c0]);
                if (de < bv || (de == bv && c0 < bi)) { bv = de; bi = c0; }
            }
        } else {
            // candidate list overflowed: guaranteed-exact full scan (rare)
            for (int col = sl; col < NK; col += 4) {
                float acc = dot_exact(a4, (const float4*)(W + (size_t)col * ND));
                float de = __fadd_rn(__fsub_rn(A, __fmul_rn(2.f, acc)), Ns[col]);
                if (de < bv || (de == bv && col < bi)) { bv = de; bi = col; }
            }
        }
        pbv[row * 4 + sl] = bv;
        pbi[row * 4 + sl] = bi;
    }
    __syncthreads();
    if (tid < TM) {
        float bv = pbv[tid * 4]; int bi = pbi[tid * 4];
        #pragma unroll
        for (int t = 1; t < 4; t++) {
            float v = pbv[tid * 4 + t]; int ii = pbi[tid * 4 + t];
            if (v < bv || (v == bv && ii < bi)) { bv = v; bi = ii; }
        }
        if (bi >= NK) bi = 0;               // unreachable by construction
        RowIdx[tid] = bi;
        if (write_idx) {
            int nn = row0 + tid;
            int b = nn >> 11;               // T = 2048
            int t = nn & (NT - 1);
            idx_out[(size_t)b * NL * NT + (size_t)l * NT + t] = (float)bi;
        }
    }
    __syncthreads();

    // ---- residual -= gathered code ----
    {
        float4*       gout = (float4*)(g_res + (size_t)row0 * ND);
        const float4* gin  = (const float4*)gA;
        #pragma unroll
        for (int it = 0; it < (TM * (ND / 4)) / NTHREADS; it++) {
            int e   = tid + it * NTHREADS;
            int row = e >> 6;
            int d4  = e & 63;
            float4 w4 = *(const float4*)(W + (size_t)RowIdx[row] * ND + 4 * d4);
            float4 a4v = gin[e];
            gout[e] = make_float4(__fsub_rn(a4v.x, w4.x), __fsub_rn(a4v.y, w4.y),
                                  __fsub_rn(a4v.z, w4.z), __fsub_rn(a4v.w, w4.w));
        }
    }
    #undef WSIDX
}

// ---------------------------------------------------------------- launch
extern "C" void kernel_launch(void* const* d_in, const int* in_sizes, int n_in,
                              void* d_out, int out_size) {
    const float* x  = (const float*)d_in[0];
    const float* cb = (const float*)d_in[1];
    if (n_in >= 2 && in_sizes[0] == NL * NK * ND && in_sizes[1] == NB * ND * NT) {
        const float* t = x; x = cb; cb = t;
    }
    float* out = (float*)d_out;
    int write_idx = (out_size >= NOUT + NIDX) ? 1 : 0;

    cudaFuncSetAttribute(vq_layer_kernel,
                         cudaFuncAttributeMaxDynamicSharedMemorySize, SMEM_BYTES);

    norms_kernel<<<(NL * NK * 32 + 255) / 256, 256>>>(cb);
    pack_kernel<<<NL * NSTG * 512 / 256, 256>>>(cb);

    dim3 tb(32, 8);
    tin_kernel<<<dim3(NT / 32, ND / 32, NB), tb>>>(x);

    for (int l = 0; l < NL; l++)
        vq_layer_kernel<<<NVEC / TM, NTHREADS, SMEM_BYTES>>>(cb, out + NOUT, l, write_idx);

    tout_kernel<<<dim3(NT / 32, ND / 32, NB), tb>>>(x, out);
}

// round 16
// speedup vs baseline: 1.3072x; 1.3072x over previous
#include <cuda_runtime.h>
#include <cstdint>

#define NB 32
#define ND 256
#define NT 2048
#define NL 8
#define NK 1024
#define NVEC (NB*NT)
#define NOUT (NB*ND*NT)
#define NIDX (NB*NL*NT)

#define TM 128                       // rows per CTA
#define NTHREADS 256
#define TILEN 128                    // codes per ntile
#define NSTG 64                      // total stages (ntile x dchunk)
#define CAP 32

// SMEM layout (bytes) — no B staging buffers
#define ATF_OFF 0                    // A fp16 fragments: 4096 uint4 = 65536
#define NS_OFF  65536                // 1024 f32
#define AN_OFF  69632                // 128 f32
#define EE_OFF  70144                // 128 f32 (precomputed screen window)
#define RM_OFF  70656                // 128 u32
#define CNT_OFF 71168                // 128 i32
#define RI_OFF  71680                // 128 i32
#define CD_OFF  72192                // 128*CAP u32 = 16384
#define PBV_OFF 88576                // 128*2 f32
#define PBI_OFF 89600                // 128*2 i32
#define SMEM_BYTES 90624             // x2 CTAs = 181248 <= 227KB/SM

// Scratch (static device allocations are the sanctioned workaround)
__device__ float    g_res[(size_t)NVEC * ND];
__device__ float    g_norms[NL * NK];
__device__ unsigned g_nsmax[NL];
__device__ uint4    g_wpack[NL * NSTG * 512];   // fragment-major fp16 codebook (4MB)

typedef unsigned long long ull;

// ---------------------------------------------------------------- helpers
__device__ __forceinline__ uint32_t h2f16(float lo, float hi) {
    uint32_t r; asm("cvt.rn.f16x2.f32 %0, %1, %2;" : "=r"(r) : "f"(hi), "f"(lo));
    return r;
}
__device__ __forceinline__ void mma_f16(float* c, const uint32_t* a,
                                        uint32_t b0, uint32_t b1) {
    asm volatile(
        "mma.sync.aligned.m16n8k16.row.col.f32.f16.f16.f32 "
        "{%0,%1,%2,%3}, {%4,%5,%6,%7}, {%8,%9}, {%0,%1,%2,%3};"
        : "+f"(c[0]), "+f"(c[1]), "+f"(c[2]), "+f"(c[3])
        : "r"(a[0]), "r"(a[1]), "r"(a[2]), "r"(a[3]), "r"(b0), "r"(b1));
}
__device__ __forceinline__ ull pack2(float a, float b) {
    ull r; asm("mov.b64 %0, {%1, %2};" : "=l"(r) : "f"(a), "f"(b)); return r;
}
__device__ __forceinline__ float2 unpack2(ull v) {
    float2 r; asm("mov.b64 {%0, %1}, %2;" : "=f"(r.x), "=f"(r.y) : "l"(v)); return r;
}
__device__ __forceinline__ ull ffma2(ull a, ull b, ull c) {
    ull d; asm("fma.rn.f32x2 %0, %1, %2, %3;" : "=l"(d) : "l"(a), "l"(b), "l"(c));
    return d;
}
__device__ __forceinline__ ull fadd2(ull a, ull b) {
    ull d; asm("add.rn.f32x2 %0, %1, %2;" : "=l"(d) : "l"(a), "l"(b));
    return d;
}

// XLA-style warp row-reduce (mul then add, NO fma), xor-butterfly tree.
__device__ __forceinline__ float warp_sumsq_x32(const float* __restrict__ p, int lane) {
    float s = 0.f;
    #pragma unroll
    for (int i = 0; i < ND / 32; i++) {
        float v = p[lane + 32 * i];
        s = __fadd_rn(s, __fmul_rn(v, v));
    }
    #pragma unroll
    for (int o = 16; o; o >>= 1)
        s = __fadd_rn(s, __shfl_xor_sync(0xffffffffu, s, o));
    return s;
}

// exact dot chain (ascending d, fmaf) — validated rounding sequence.
__device__ __forceinline__ float dot_exact(const float4* __restrict__ a4,
                                           const float4* __restrict__ w4) {
    float acc = 0.f;
    #pragma unroll 8
    for (int q = 0; q < ND / 4; q++) {
        float4 av = a4[q], wv = w4[q];
        acc = __fmaf_rn(av.x, wv.x, acc);
        acc = __fmaf_rn(av.y, wv.y, acc);
        acc = __fmaf_rn(av.z, wv.z, acc);
        acc = __fmaf_rn(av.w, wv.w, acc);
    }
    return acc;
}

// ---------------------------------------------------------------- codebook norms
__global__ void norms_kernel(const float* __restrict__ cb) {
    int w    = (blockIdx.x * blockDim.x + threadIdx.x) >> 5;
    int lane = threadIdx.x & 31;
    if (w >= NL * NK) return;
    float s = warp_sumsq_x32(cb + (size_t)w * ND, lane);
    if (lane == 0) {
        g_norms[w] = s;
        atomicMax(&g_nsmax[w >> 10], __float_as_uint(s));
    }
}

// ---------------------------------------------------------------- pack codebook -> fp16 fragments
// slot within stage = ((kg*2+ng)*4+pp)*32 + lane; stage = ntile*8+dchunk
__global__ void pack_kernel(const float* __restrict__ cb) {
    int gid  = blockIdx.x * blockDim.x + threadIdx.x;   // 0 .. NL*64*512-1
    int lane = gid & 31;
    int s16  = (gid >> 5) & 15;
    int pp   = s16 & 3, ng = (s16 >> 2) & 1, kg = s16 >> 3;
    int st   = (gid >> 9) & 63;
    int l    = gid >> 15;
    int code = (st >> 3) * TILEN + ng * 64 + pp * 16 + (lane >> 2);
    int d    = (st & 7) * 32 + kg * 16 + (lane & 3) * 2;
    const float* w = cb + ((size_t)l * NK + code) * ND + d;
    uint4 v;
    v.x = h2f16(w[0], w[1]);
    v.y = h2f16(w[8], w[9]);
    v.z = h2f16(w[8 * ND], w[8 * ND + 1]);
    v.w = h2f16(w[8 * ND + 8], w[8 * ND + 9]);
    g_wpack[gid] = v;
}

// ---------------------------------------------------------------- x (B,D,T) -> res (N,D)
__global__ void tin_kernel(const float* __restrict__ x) {
    __shared__ float tile[32][33];
    int b  = blockIdx.z;
    int d0 = blockIdx.y * 32, t0 = blockIdx.x * 32;
    int tx = threadIdx.x, ty = threadIdx.y;
    #pragma unroll
    for (int i = 0; i < 32; i += 8)
        tile[ty + i][tx] = x[((size_t)b * ND + d0 + ty + i) * NT + t0 + tx];
    __syncthreads();
    #pragma unroll
    for (int i = 0; i < 32; i += 8)
        g_res[((size_t)(b * NT + t0 + ty + i)) * ND + d0 + tx] = tile[tx][ty + i];
}

// ---------------------------------------------------------------- out = x - res
__global__ void tout_kernel(const float* __restrict__ x, float* __restrict__ out) {
    __shared__ float tile[32][33];
    int b  = blockIdx.z;
    int d0 = blockIdx.y * 32, t0 = blockIdx.x * 32;
    int tx = threadIdx.x, ty = threadIdx.y;
    #pragma unroll
    for (int i = 0; i < 32; i += 8)
        tile[ty + i][tx] = g_res[((size_t)(b * NT + t0 + ty + i)) * ND + d0 + tx];
    __syncthreads();
    size_t base = (size_t)b * ND * NT;
    #pragma unroll
    for (int i = 0; i < 32; i += 8) {
        size_t o = base + (size_t)(d0 + ty + i) * NT + t0 + tx;
        out[o] = __fsub_rn(x[o], tile[tx][ty + i]);
    }
}

// ---------------------------------------------------------------- one RVQ layer
__global__ void __launch_bounds__(NTHREADS, 2) vq_layer_kernel(
    const float* __restrict__ codebooks,
    float* __restrict__ idx_out,
    int l, int write_idx)
{
    extern __shared__ char smem[];
    uint4*    Atf4   = (uint4*)(smem + ATF_OFF);
    float*    Ns     = (float*)(smem + NS_OFF);
    float*    An     = (float*)(smem + AN_OFF);
    float*    Ee     = (float*)(smem + EE_OFF);
    uint32_t* runmin = (uint32_t*)(smem + RM_OFF);
    int*      cnt    = (int*)(smem + CNT_OFF);
    int*      RowIdx = (int*)(smem + RI_OFF);
    uint32_t* cand   = (uint32_t*)(smem + CD_OFF);
    float*    pbv    = (float*)(smem + PBV_OFF);
    int*      pbi    = (int*)(smem + PBI_OFF);

    const float* W  = codebooks + (size_t)l * NK * ND;
    const int row0  = blockIdx.x * TM;
    const float* gA = g_res + (size_t)row0 * ND;
    const int tid   = threadIdx.x;
    const int lane  = tid & 31;
    const int warp  = tid >> 5;
    const int mg    = warp & 1;        // M-group (64 rows)
    const int ng    = warp >> 1;       // N-group (32 cols within ntile)
    const int lr    = lane >> 2, lc = lane & 3;
    const float nsM = __uint_as_float(g_nsmax[l]);

    for (int i = tid; i < NK; i += NTHREADS) Ns[i] = g_norms[l * NK + i];
    if (tid < TM) { cnt[tid] = 0; runmin[tid] = 0x7F7FFFFFu; }

    // ---- |r|^2 per row, XLA reduce order ----
    #pragma unroll
    for (int rr = 0; rr < TM / 8; rr++) {
        int r = rr * 8 + warp;
        float s = warp_sumsq_x32(&gA[(size_t)r * ND], lane);
        if (lane == 0) An[r] = s;
    }

    // ---- pack A as fp16 m16n8k16 fragments (once per layer) ----
    #pragma unroll
    for (int i = 0; i < 4096 / NTHREADS; i++) {
        int s   = tid + i * NTHREADS;
        int lb  = s & 31, kq = (s >> 5) & 15, mt = (s >> 9) & 1, mgi = s >> 10;
        int r   = mgi * 32 + mt * 16 + (lb >> 2);
        int k0  = kq * 16 + (lb & 3) * 2;
        float2 x0 = *(const float2*)(gA + (size_t)r * ND + k0);
        float2 x1 = *(const float2*)(gA + (size_t)(r + 8) * ND + k0);
        float2 x2 = *(const float2*)(gA + (size_t)r * ND + k0 + 8);
        float2 x3 = *(const float2*)(gA + (size_t)(r + 8) * ND + k0 + 8);
        Atf4[s] = make_uint4(h2f16(x0.x, x0.y), h2f16(x1.x, x1.y),
                             h2f16(x2.x, x2.y), h2f16(x3.x, x3.y));
    }
    __syncthreads();
    // fp16 screen window: 2 * (2*2^-11*1.01) * sqrt(An*NsMax) + composition slop
    if (tid < TM) Ee[tid] = 0.00198f * sqrtf(An[tid] * nsM) + 0.25f;
    __syncthreads();     // A buffer + Ee ready; NO barriers in mainloop after this

    // ---- per-warp B fragment slot addresses in g_wpack ----
    const uint4* wp = (const uint4*)g_wpack + (size_t)l * NSTG * 512;
    const int ngh = ng >> 1, ngl = ng & 1;
    int sb[4];
    #pragma unroll
    for (int kg = 0; kg < 2; kg++)
        #pragma unroll
        for (int p = 0; p < 2; p++)
            sb[kg * 2 + p] = ((kg * 2 + ngh) * 4 + ngl * 2 + p) * 32 + lane;

    const ull NEG2 = pack2(-2.f, -2.f);

    uint4 BA[4], BB[4];
    #pragma unroll
    for (int q = 0; q < 4; q++) BA[q] = wp[sb[q]];   // stage 0

    float accf[4][4][4];
    for (int t2 = 0; t2 < NSTG; t2 += 2) {
        if ((t2 & 7) == 0) {
            #pragma unroll
            for (int a = 0; a < 4; a++)
                #pragma unroll
                for (int b = 0; b < 4; b++)
                    #pragma unroll
                    for (int c = 0; c < 4; c++) accf[a][b][c] = 0.f;
        }
        // prefetch odd stage into BB, compute even stage from BA
        {
            const uint4* wn = wp + (size_t)(t2 + 1) * 512;
            #pragma unroll
            for (int q = 0; q < 4; q++) BB[q] = wn[sb[q]];
        }
        #pragma unroll
        for (int kg = 0; kg < 2; kg++) {
            const int kq = (t2 & 7) * 2 + kg;
            uint4 Af[4];
            #pragma unroll
            for (int mt = 0; mt < 4; mt++)
                Af[mt] = Atf4[((mg * 4 + mt) * 16 + kq) * 32 + lane];
            #pragma unroll
            for (int mt = 0; mt < 4; mt++) {
                uint32_t a[4] = {Af[mt].x, Af[mt].y, Af[mt].z, Af[mt].w};
                #pragma unroll
                for (int ns = 0; ns < 4; ns++) {
                    uint4 B = BA[kg * 2 + (ns >> 1)];
                    mma_f16(accf[mt][ns], a, (ns & 1) ? B.z : B.x,
                                             (ns & 1) ? B.w : B.y);
                }
            }
        }
        // prefetch next even stage into BA, compute odd stage from BB
        {
            const uint4* wn = wp + (size_t)((t2 + 2 < NSTG) ? t2 + 2 : t2) * 512;
            #pragma unroll
            for (int q = 0; q < 4; q++) BA[q] = wn[sb[q]];
        }
        #pragma unroll
        for (int kg = 0; kg < 2; kg++) {
            const int kq = ((t2 + 1) & 7) * 2 + kg;
            uint4 Af[4];
            #pragma unroll
            for (int mt = 0; mt < 4; mt++)
                Af[mt] = Atf4[((mg * 4 + mt) * 16 + kq) * 32 + lane];
            #pragma unroll
            for (int mt = 0; mt < 4; mt++) {
                uint32_t a[4] = {Af[mt].x, Af[mt].y, Af[mt].z, Af[mt].w};
                #pragma unroll
                for (int ns = 0; ns < 4; ns++) {
                    uint4 B = BB[kg * 2 + (ns >> 1)];
                    mma_f16(accf[mt][ns], a, (ns & 1) ? B.z : B.x,
                                             (ns & 1) ? B.w : B.y);
                }
            }
        }

        // ---- per-ntile epilogue (packed f32x2, single pass) ----
        if ((t2 & 7) == 6) {
            const int ntile = t2 >> 3;
            ull Ns2[4];
            #pragma unroll
            for (int ns = 0; ns < 4; ns++)
                Ns2[ns] = *(const ull*)&Ns[ntile * TILEN + ng * 32 + (ns >> 1) * 16
                                           + (ns & 1) * 8 + 2 * lc];
            #pragma unroll
            for (int mt = 0; mt < 4; mt++) {
                #pragma unroll
                for (int h = 0; h < 2; h++) {
                    int row = mg * 64 + mt * 16 + lr + 8 * h;
                    float A  = An[row];
                    float ee = Ee[row];
                    ull  A2  = pack2(A, A);
                    float dl[8]; float m = 3.4e38f;
                    #pragma unroll
                    for (int ns = 0; ns < 4; ns++) {
                        // dv = rn(rn(A - 2*acc) + Ns): fma(-2,acc,A) exact-equal
                        // to sub(A, mul(2,acc)) since 2*acc is exact.
                        ull acc2 = pack2(accf[mt][ns][2 * h], accf[mt][ns][2 * h + 1]);
                        float2 e = unpack2(fadd2(ffma2(acc2, NEG2, A2), Ns2[ns]));
                        dl[2 * ns] = e.x; dl[2 * ns + 1] = e.y;
                        m = fminf(m, fminf(e.x, e.y));
                    }
                    float m2 = fminf(m, __shfl_xor_sync(0xffffffffu, m, 1));
                    m2 = fminf(m2, __shfl_xor_sync(0xffffffffu, m2, 2));
                    float rm  = __uint_as_float(runmin[row]);    // racy = conservative
                    float thr = fminf(m2, rm) + ee;
                    #pragma unroll
                    for (int e8 = 0; e8 < 8; e8++) {
                        if (dl[e8] <= thr) {
                            int col = ntile * TILEN + ng * 32 + ((e8 >> 2) & 1) * 16
                                    + ((e8 >> 1) & 1) * 8 + 2 * lc + (e8 & 1);
                            int slot = atomicAdd(&cnt[row], 1);
                            if (slot < CAP)
                                cand[row * CAP + slot] =
                                    (__float_as_uint(fmaxf(dl[e8], 0.f)) & 0xFFFFFC00u)
                                    | (uint32_t)col;
                        }
                    }
                    if (lc == 0)
                        atomicMin(runmin + row, __float_as_uint(fmaxf(m2, 0.f)));
                }
            }
        }
    }
    __syncthreads();

    // ---- exact rescore: float4 loads + ILP-2 candidate pairs (bit-identical) ----
    {
        int row = tid & (TM - 1), sl = tid >> 7;
        float A = An[row];
        float thrF = __uint_as_float(runmin[row]) + Ee[row];
        int n = cnt[row];
        float bv = 3.4e38f; int bi = 1 << 30;
        const float4* a4 = (const float4*)(gA + (size_t)row * ND);
        if (n <= CAP) {
            int mycols[CAP / 2]; int mc = 0;
            for (int s = sl; s < n; s += 2) {
                uint32_t u = cand[row * CAP + s];
                if (__uint_as_float(u & 0xFFFFFC00u) > thrF) continue;
                mycols[mc++] = (int)(u & 1023u);
            }
            int i = 0;
            for (; i + 1 < mc; i += 2) {
                int c0 = mycols[i], c1 = mycols[i + 1];
                const float4* w0 = (const float4*)(W + (size_t)c0 * ND);
                const float4* w1 = (const float4*)(W + (size_t)c1 * ND);
                float acc0 = 0.f, acc1 = 0.f;
                #pragma unroll 8
                for (int q = 0; q < ND / 4; q++) {
                    float4 av = a4[q], v0 = w0[q], v1 = w1[q];
                    acc0 = __fmaf_rn(av.x, v0.x, acc0);
                    acc1 = __fmaf_rn(av.x, v1.x, acc1);
                    acc0 = __fmaf_rn(av.y, v0.y, acc0);
                    acc1 = __fmaf_rn(av.y, v1.y, acc1);
                    acc0 = __fmaf_rn(av.z, v0.z, acc0);
                    acc1 = __fmaf_rn(av.z, v1.z, acc1);
                    acc0 = __fmaf_rn(av.w, v0.w, acc0);
                    acc1 = __fmaf_rn(av.w, v1.w, acc1);
                }
                float d0 = __fadd_rn(__fsub_rn(A, __fmul_rn(2.f, acc0)), Ns[c0]);
                float d1 = __fadd_rn(__fsub_rn(A, __fmul_rn(2.f, acc1)), Ns[c1]);
                if (d0 < bv || (d0 == bv && c0 < bi)) { bv = d0; bi = c0; }
                if (d1 < bv || (d1 == bv && c1 < bi)) { bv = d1; bi = c1; }
            }
            if (i < mc) {
                int c0 = mycols[i];
                float acc = dot_exact(a4, (const float4*)(W + (size_t)c0 * ND));
                float de = __fadd_rn(__fsub_rn(A, __fmul_rn(2.f, acc)), Ns[c0]);
                if (de < bv || (de == bv && c0 < bi)) { bv = de; bi = c0; }
            }
        } else {
            // candidate list overflowed: guaranteed-exact full scan (rare)
            for (int col = sl; col < NK; col += 2) {
                float acc = dot_exact(a4, (const float4*)(W + (size_t)col * ND));
                float de = __fadd_rn(__fsub_rn(A, __fmul_rn(2.f, acc)), Ns[col]);
                if (de < bv || (de == bv && col < bi)) { bv = de; bi = col; }
            }
        }
        pbv[row * 2 + sl] = bv;
        pbi[row * 2 + sl] = bi;
    }
    __syncthreads();
    if (tid < TM) {
        float bv = pbv[tid * 2]; int bi = pbi[tid * 2];
        float v = pbv[tid * 2 + 1]; int ii = pbi[tid * 2 + 1];
        if (v < bv || (v == bv && ii < bi)) { bv = v; bi = ii; }
        if (bi >= NK) bi = 0;               // unreachable by construction
        RowIdx[tid] = bi;
        if (write_idx) {
            int nn = row0 + tid;
            int b = nn >> 11;               // T = 2048
            int t = nn & (NT - 1);
            idx_out[(size_t)b * NL * NT + (size_t)l * NT + t] = (float)bi;
        }
    }
    __syncthreads();

    // ---- residual -= gathered code ----
    {
        float4*       gout = (float4*)(g_res + (size_t)row0 * ND);
        const float4* gin  = (const float4*)gA;
        #pragma unroll
        for (int it = 0; it < (TM * (ND / 4)) / NTHREADS; it++) {
            int e   = tid + it * NTHREADS;
            int row = e >> 6;
            int d4  = e & 63;
            float4 w4 = *(const float4*)(W + (size_t)RowIdx[row] * ND + 4 * d4);
            float4 a4v = gin[e];
            gout[e] = make_float4(__fsub_rn(a4v.x, w4.x), __fsub_rn(a4v.y, w4.y),
                                  __fsub_rn(a4v.z, w4.z), __fsub_rn(a4v.w, w4.w));
        }
    }
}

// ---------------------------------------------------------------- launch
extern "C" void kernel_launch(void* const* d_in, const int* in_sizes, int n_in,
                              void* d_out, int out_size) {
    const float* x  = (const float*)d_in[0];
    const float* cb = (const float*)d_in[1];
    if (n_in >= 2 && in_sizes[0] == NL * NK * ND && in_sizes[1] == NB * ND * NT) {
        const float* t = x; x = cb; cb = t;
    }
    float* out = (float*)d_out;
    int write_idx = (out_size >= NOUT + NIDX) ? 1 : 0;

    cudaFuncSetAttribute(vq_layer_kernel,
                         cudaFuncAttributeMaxDynamicSharedMemorySize, SMEM_BYTES);

    norms_kernel<<<(NL * NK * 32 + 255) / 256, 256>>>(cb);
    pack_kernel<<<NL * NSTG * 512 / 256, 256>>>(cb);

    dim3 tb(32, 8);
    tin_kernel<<<dim3(NT / 32, ND / 32, NB), tb>>>(x);

    for (int l = 0; l < NL; l++)
        vq_layer_kernel<<<NVEC / TM, NTHREADS, SMEM_BYTES>>>(cb, out + NOUT, l, write_idx);

    tout_kernel<<<dim3(NT / 32, ND / 32, NB), tb>>>(x, out);
}